// round 11
// baseline (speedup 1.0000x reference)
#include <cuda_runtime.h>
#include <cstdint>

#define Nn 4096
#define WORDS 128          // 4096 bits / 32
#define TI 16              // i-rows per block (register blocking)
#define JSPLIT 4           // split j-range across blocks
#define PACK_BLOCKS 4096   // 16KB of A per block — balanced vs rowsum blocks
#define ROWSUM_BLOCKS Nn

// Scratch (device globals — no allocation allowed)
__device__ uint32_t g_bitsT[WORDS * Nn];   // plane-major: word w of row j at [w*Nn + j]
__device__ __align__(16) uint32_t g_bitsR[Nn * WORDS];  // row-major copy (i-tile loads)
__device__ __align__(16) float g_e[Nn];    // row sums of edge_features
__device__ __align__(16) float g_agg[Nn];  // aggregated[i]

// ---------------------------------------------------------------------------
// K1 (fused): blocks [0, PACK_BLOCKS) bit-pack adjacency.
//   FMA packing: A values are exactly {0.0,1.0}, so the byte for 8 cols is
//   a dot product with powers of two — 7 FFMA + 1 F2I replaces ~16 cmp/or.
//   Diagonal bit cleared at the word-write site (amortized, exact).
// blocks [PACK_BLOCKS, ...) row-sum E and zero g_agg.
// ---------------------------------------------------------------------------
__global__ void prep_kernel(const float* __restrict__ A,
                            const float* __restrict__ E) {
    if (blockIdx.x < PACK_BLOCKS) {
        int lane = threadIdx.x & 31;
        int warpid = blockIdx.x * 8 + (threadIdx.x >> 5);   // 0..32767
        const int NW = PACK_BLOCKS * 8;                     // 32768 warps
        unsigned q = lane >> 2;                             // word-in-group (0..7)
        unsigned grpmask = 0xFu << (q << 2);
        unsigned sh = (lane & 3) * 8;
        // groups of 256 cols: Nn*16 = 65536 total, exactly 2 per warp
        #pragma unroll
        for (int o = 0; o < 2; o++) {
            int gg  = warpid + o * NW;
            int j   = gg >> 4;
            int grp = gg & 15;
            int col = (grp << 8) + (lane << 3);
            const float4* p = (const float4*)(A + (size_t)j * Nn + col);
            float4 v0 = p[0];
            float4 v1 = p[1];
            float f = v0.x;
            f = fmaf(v0.y,   2.f, f);
            f = fmaf(v0.z,   4.f, f);
            f = fmaf(v0.w,   8.f, f);
            f = fmaf(v1.x,  16.f, f);
            f = fmaf(v1.y,  32.f, f);
            f = fmaf(v1.z,  64.f, f);
            f = fmaf(v1.w, 128.f, f);
            unsigned byte = (unsigned)f;          // exact: sum of distinct powers of 2
            unsigned word = __reduce_or_sync(grpmask, byte << sh);
            if ((lane & 3) == 0) {
                int w = (grp << 3) + (int)q;
                if (w == (j >> 5)) word &= ~(1u << (j & 31));   // clear diag bit
                g_bitsT[w * Nn + j] = word;          // plane-major (j-side)
                g_bitsR[j * WORDS + w] = word;       // row-major (i-side)
            }
        }
    } else {
        int j = blockIdx.x - PACK_BLOCKS;
        const float4* row = (const float4*)(E + (size_t)j * Nn);
        int tid = threadIdx.x;
        float s = 0.f;
        #pragma unroll
        for (int k = 0; k < 4; k++) {
            float4 v = row[tid + 256 * k];
            s += (v.x + v.y) + (v.z + v.w);
        }
        s += __shfl_down_sync(0xffffffffu, s, 16);
        s += __shfl_down_sync(0xffffffffu, s, 8);
        s += __shfl_down_sync(0xffffffffu, s, 4);
        s += __shfl_down_sync(0xffffffffu, s, 2);
        s += __shfl_down_sync(0xffffffffu, s, 1);
        __shared__ float sp[8];
        int lane = tid & 31, wid = tid >> 5;
        if (lane == 0) sp[wid] = s;
        __syncthreads();
        if (tid == 0) {
            float t = 0.f;
            #pragma unroll
            for (int k = 0; k < 8; k++) t += sp[k];
            g_e[j] = t;
            g_agg[j] = 0.f;
        }
    }
}

// ---------------------------------------------------------------------------
// K2: agg[i] = sum_j [ (i!=j) && (B_i & B_j != empty) ] * e[j]
// SUBTRACT-ON-MISS fast path (miss prob ~1e-4 per pair). i-tile loaded
// COALESCED from the row-major copy. Diagonal corrected once post-loop.
// ---------------------------------------------------------------------------
__global__ void agg_kernel() {
    int tid = threadIdx.x;
    __shared__ uint32_t sBi[TI * WORDS];
    __shared__ int sNe[TI];           // row-nonempty flag (for diag fix)
    __shared__ float sPart[8][TI];
    int i0 = blockIdx.x * TI;

    if (tid < TI) sNe[tid] = 0;
    __syncthreads();
    // coalesced i-tile load: TI*WORDS words = 8KB contiguous (uint4-wide)
    {
        const uint4* src = (const uint4*)(g_bitsR + (size_t)i0 * WORDS);
        uint4* dst = (uint4*)sBi;
        #pragma unroll
        for (int k = 0; k < (TI * WORDS / 4) / 256; k++) {
            uint4 v = src[tid + 256 * k];
            dst[tid + 256 * k] = v;
            if (v.x | v.y | v.z | v.w) sNe[(tid + 256 * k) >> 5] = 1;
        }
    }
    __syncthreads();

    int jBeg = blockIdx.y * (Nn / JSPLIT);
    int jEnd = jBeg + (Nn / JSPLIT);

    // this thread's share of sum(e) over its j set
    float sumE = 0.f;
    for (int j = jBeg + tid; j < jEnd; j += blockDim.x) sumE += g_e[j];

    uint32_t bi0[TI];
    float acc[TI];
    #pragma unroll
    for (int r = 0; r < TI; r++) { bi0[r] = sBi[r * WORDS]; acc[r] = sumE; }

    for (int j = jBeg + tid; j < jEnd; j += blockDim.x) {
        uint32_t b0 = g_bitsT[j];     // word-0 plane: 16KB, cache-resident
        unsigned zmask = 0;
        #pragma unroll
        for (int r = 0; r < TI; r++) {
            if (!(bi0[r] & b0)) zmask |= (1u << r);
        }
        if (zmask) {                  // rare (~1e-4 per pair)
            float e = g_e[j];
            do {
                int r = __ffs(zmask) - 1;
                zmask &= zmask - 1;
                bool hit = false;
                for (int w = 1; w < WORDS; w++)
                    if (sBi[r * WORDS + w] & g_bitsT[w * Nn + j]) { hit = true; break; }
                if (!hit) acc[r] -= e;
            } while (zmask);
        }
    }

    int lane = tid & 31, wid = tid >> 5;
    #pragma unroll
    for (int r = 0; r < TI; r++) {
        float v = acc[r];
        v += __shfl_down_sync(0xffffffffu, v, 16);
        v += __shfl_down_sync(0xffffffffu, v, 8);
        v += __shfl_down_sync(0xffffffffu, v, 4);
        v += __shfl_down_sync(0xffffffffu, v, 2);
        v += __shfl_down_sync(0xffffffffu, v, 1);
        if (lane == 0) sPart[wid][r] = v;
    }
    __syncthreads();
    if (tid < TI) {
        float s = 0.f;
        #pragma unroll
        for (int w = 0; w < 8; w++) s += sPart[w][tid];
        // diagonal correction, applied exactly once (by the owning chunk)
        int i = i0 + tid;
        if (i >= jBeg && i < jEnd && sNe[tid]) s -= g_e[i];
        atomicAdd(&g_agg[i], s);
    }
}

// ---------------------------------------------------------------------------
// K3: out[o] = b[o] + dot(W[o,:], agg)
// One BLOCK (256 threads) per output row -> 4096 blocks, full occupancy.
// ---------------------------------------------------------------------------
__global__ void gemv_kernel(const float* __restrict__ Wm,
                            const float* __restrict__ bias,
                            float* __restrict__ out) {
    int o = blockIdx.x;
    int tid = threadIdx.x;
    const float4* wr = (const float4*)(Wm + (size_t)o * Nn);
    const float4* ar = (const float4*)g_agg;

    float4 w0 = wr[tid];
    float4 w1 = wr[tid + 256];
    float4 w2 = wr[tid + 512];
    float4 w3 = wr[tid + 768];
    float4 a0 = ar[tid];
    float4 a1 = ar[tid + 256];
    float4 a2 = ar[tid + 512];
    float4 a3 = ar[tid + 768];
    float s0 = w0.x * a0.x + w0.y * a0.y + w0.z * a0.z + w0.w * a0.w;
    float s1 = w1.x * a1.x + w1.y * a1.y + w1.z * a1.z + w1.w * a1.w;
    float s2 = w2.x * a2.x + w2.y * a2.y + w2.z * a2.z + w2.w * a2.w;
    float s3 = w3.x * a3.x + w3.y * a3.y + w3.z * a3.z + w3.w * a3.w;
    float s = (s0 + s1) + (s2 + s3);

    s += __shfl_down_sync(0xffffffffu, s, 16);
    s += __shfl_down_sync(0xffffffffu, s, 8);
    s += __shfl_down_sync(0xffffffffu, s, 4);
    s += __shfl_down_sync(0xffffffffu, s, 2);
    s += __shfl_down_sync(0xffffffffu, s, 1);
    __shared__ float sp[8];
    int lane = tid & 31, wid = tid >> 5;
    if (lane == 0) sp[wid] = s;
    __syncthreads();
    if (tid == 0) {
        float t = 0.f;
        #pragma unroll
        for (int k = 0; k < 8; k++) t += sp[k];
        out[o] = t + bias[o];
    }
}

extern "C" void kernel_launch(void* const* d_in, const int* in_sizes, int n_in,
                              void* d_out, int out_size) {
    const float* A  = (const float*)d_in[0];  // adjacency [N,N]
    const float* E  = (const float*)d_in[1];  // edge_features [N,F]
    const float* Wm = (const float*)d_in[2];  // W [OUT,N]
    const float* b  = (const float*)d_in[3];  // b [OUT]
    float* out = (float*)d_out;

    prep_kernel<<<PACK_BLOCKS + ROWSUM_BLOCKS, 256>>>(A, E);
    dim3 g2(Nn / TI, JSPLIT);
    agg_kernel<<<g2, 256>>>();
    gemv_kernel<<<Nn, 256>>>(Wm, b, out);
}

// round 12
// speedup vs baseline: 1.0395x; 1.0395x over previous
#include <cuda_runtime.h>
#include <cstdint>

#define Nn 4096
#define WORDS 128          // 4096 bits / 32
#define TI 16              // i-rows per agg block (register blocking)
#define JSPLIT 4           // j-range split
#define AGG_BLOCKS ((Nn / TI) * JSPLIT)   // 1024, bids 0..1023 (wave-1 resident)
#define PACK_BLOCKS 4096   // 16KB of A per block — balanced vs rowsum blocks

// Scratch (device globals — no allocation allowed)
__device__ __align__(16) uint32_t g_bitsR[Nn * WORDS];  // row-major bitsets
__device__ __align__(16) uint32_t g_w0[Nn];             // word-0 plane (fast test)
__device__ __align__(16) float g_e[Nn];    // row sums of edge_features
__device__ __align__(16) float g_agg[Nn];  // aggregated[i]
__device__ unsigned g_cnt;                 // agg completion counter

// ---------------------------------------------------------------------------
// K1 (fused): blocks [0, PACK_BLOCKS) bit-pack adjacency (FMA packing; diag
// bit cleared at write site). Row-major layout only — writes are contiguous.
// blocks [PACK_BLOCKS, ...) row-sum E, zero g_agg, zero g_cnt.
// ---------------------------------------------------------------------------
__global__ void prep_kernel(const float* __restrict__ A,
                            const float* __restrict__ E) {
    if (blockIdx.x < PACK_BLOCKS) {
        int lane = threadIdx.x & 31;
        int warpid = blockIdx.x * 8 + (threadIdx.x >> 5);   // 0..32767
        const int NW = PACK_BLOCKS * 8;                     // 32768 warps
        unsigned q = lane >> 2;                             // word-in-group (0..7)
        unsigned grpmask = 0xFu << (q << 2);
        unsigned sh = (lane & 3) * 8;
        // groups of 256 cols: Nn*16 = 65536 total, exactly 2 per warp
        #pragma unroll
        for (int o = 0; o < 2; o++) {
            int gg  = warpid + o * NW;
            int j   = gg >> 4;
            int grp = gg & 15;
            int col = (grp << 8) + (lane << 3);
            const float4* p = (const float4*)(A + (size_t)j * Nn + col);
            float4 v0 = __ldcs(p);
            float4 v1 = __ldcs(p + 1);
            float f = v0.x;
            f = fmaf(v0.y,   2.f, f);
            f = fmaf(v0.z,   4.f, f);
            f = fmaf(v0.w,   8.f, f);
            f = fmaf(v1.x,  16.f, f);
            f = fmaf(v1.y,  32.f, f);
            f = fmaf(v1.z,  64.f, f);
            f = fmaf(v1.w, 128.f, f);
            unsigned byte = (unsigned)f;          // exact: sum of distinct powers of 2
            unsigned word = __reduce_or_sync(grpmask, byte << sh);
            if ((lane & 3) == 0) {
                int w = (grp << 3) + (int)q;
                if (w == (j >> 5)) word &= ~(1u << (j & 31));   // clear diag bit
                g_bitsR[j * WORDS + w] = word;
                if (w == 0) g_w0[j] = word;
            }
        }
    } else {
        int j = blockIdx.x - PACK_BLOCKS;
        const float4* row = (const float4*)(E + (size_t)j * Nn);
        int tid = threadIdx.x;
        float s = 0.f;
        #pragma unroll
        for (int k = 0; k < 4; k++) {
            float4 v = __ldcs(row + tid + 256 * k);
            s += (v.x + v.y) + (v.z + v.w);
        }
        s += __shfl_down_sync(0xffffffffu, s, 16);
        s += __shfl_down_sync(0xffffffffu, s, 8);
        s += __shfl_down_sync(0xffffffffu, s, 4);
        s += __shfl_down_sync(0xffffffffu, s, 2);
        s += __shfl_down_sync(0xffffffffu, s, 1);
        __shared__ float sp[8];
        int lane = tid & 31, wid = tid >> 5;
        if (lane == 0) sp[wid] = s;
        __syncthreads();
        if (tid == 0) {
            float t = 0.f;
            #pragma unroll
            for (int k = 0; k < 8; k++) t += sp[k];
            g_e[j] = t;
            g_agg[j] = 0.f;
            if (j == 0) g_cnt = 0;
        }
    }
}

// ---------------------------------------------------------------------------
// K2 (fused agg + gemv with flag handoff):
//  bids [0, AGG_BLOCKS): agg[i] via subtract-on-miss bitset test; on finish,
//    threadfence + count on g_cnt.
//  bids [AGG_BLOCKS, ...): gemv row o. W-row loads issue FIRST (streaming DRAM
//    overlaps agg compute), then spin on g_cnt, then dot with L2-fresh agg.
//  Deadlock-safe: agg blocks are the lowest bids -> wave-1 resident; refill
//  proceeds in bid order so remaining agg blocks always get slots.
// ---------------------------------------------------------------------------
__global__ void fused_kernel(const float* __restrict__ Wm,
                             const float* __restrict__ bias,
                             float* __restrict__ out) {
    int tid = threadIdx.x;

    if (blockIdx.x < AGG_BLOCKS) {
        __shared__ uint32_t sBi[TI * WORDS];
        __shared__ int sNe[TI];           // row-nonempty flag (for diag fix)
        __shared__ float sPart[8][TI];
        int tile  = blockIdx.x & ((Nn / TI) - 1);
        int chunk = blockIdx.x >> 8;      // 0..JSPLIT-1
        int i0 = tile * TI;

        if (tid < TI) sNe[tid] = 0;
        __syncthreads();
        // coalesced i-tile load: 8KB contiguous (uint4-wide)
        {
            const uint4* src = (const uint4*)(g_bitsR + (size_t)i0 * WORDS);
            uint4* dst = (uint4*)sBi;
            #pragma unroll
            for (int k = 0; k < (TI * WORDS / 4) / 256; k++) {
                uint4 v = src[tid + 256 * k];
                dst[tid + 256 * k] = v;
                if (v.x | v.y | v.z | v.w) sNe[(tid + 256 * k) >> 5] = 1;
            }
        }
        __syncthreads();

        int jBeg = chunk * (Nn / JSPLIT);
        int jEnd = jBeg + (Nn / JSPLIT);

        float sumE = 0.f;
        for (int j = jBeg + tid; j < jEnd; j += blockDim.x) sumE += g_e[j];

        uint32_t bi0[TI];
        float acc[TI];
        #pragma unroll
        for (int r = 0; r < TI; r++) { bi0[r] = sBi[r * WORDS]; acc[r] = sumE; }

        for (int j = jBeg + tid; j < jEnd; j += blockDim.x) {
            uint32_t b0 = g_w0[j];        // 16KB word-0 plane, cache-resident
            unsigned zmask = 0;
            #pragma unroll
            for (int r = 0; r < TI; r++) {
                if (!(bi0[r] & b0)) zmask |= (1u << r);
            }
            if (zmask) {                  // rare (~1e-4 per pair)
                float e = g_e[j];
                const uint32_t* bj = g_bitsR + (size_t)j * WORDS;  // contiguous
                do {
                    int r = __ffs(zmask) - 1;
                    zmask &= zmask - 1;
                    bool hit = false;
                    for (int w = 1; w < WORDS; w++)
                        if (sBi[r * WORDS + w] & bj[w]) { hit = true; break; }
                    if (!hit) acc[r] -= e;
                } while (zmask);
            }
        }

        int lane = tid & 31, wid = tid >> 5;
        #pragma unroll
        for (int r = 0; r < TI; r++) {
            float v = acc[r];
            v += __shfl_down_sync(0xffffffffu, v, 16);
            v += __shfl_down_sync(0xffffffffu, v, 8);
            v += __shfl_down_sync(0xffffffffu, v, 4);
            v += __shfl_down_sync(0xffffffffu, v, 2);
            v += __shfl_down_sync(0xffffffffu, v, 1);
            if (lane == 0) sPart[wid][r] = v;
        }
        __syncthreads();
        if (tid < TI) {
            float s = 0.f;
            #pragma unroll
            for (int w = 0; w < 8; w++) s += sPart[w][tid];
            int i = i0 + tid;
            if (i >= jBeg && i < jEnd && sNe[tid]) s -= g_e[i];  // diag fix, once
            atomicAdd(&g_agg[i], s);
        }
        __syncthreads();
        if (tid == 0) {
            __threadfence();
            atomicAdd(&g_cnt, 1u);
        }
    } else {
        // ---- gemv row: load W first (overlaps agg), then wait, then dot ----
        int o = blockIdx.x - AGG_BLOCKS;
        const float4* wr = (const float4*)(Wm + (size_t)o * Nn);
        float4 w0 = __ldcs(wr + tid);
        float4 w1 = __ldcs(wr + tid + 256);
        float4 w2 = __ldcs(wr + tid + 512);
        float4 w3 = __ldcs(wr + tid + 768);

        if (tid == 0) {
            volatile unsigned* c = &g_cnt;
            while (*c != (unsigned)AGG_BLOCKS) __nanosleep(64);
        }
        __syncthreads();

        const float4* ar = (const float4*)g_agg;
        float4 a0 = __ldcg(ar + tid);
        float4 a1 = __ldcg(ar + tid + 256);
        float4 a2 = __ldcg(ar + tid + 512);
        float4 a3 = __ldcg(ar + tid + 768);
        float s0 = w0.x * a0.x + w0.y * a0.y + w0.z * a0.z + w0.w * a0.w;
        float s1 = w1.x * a1.x + w1.y * a1.y + w1.z * a1.z + w1.w * a1.w;
        float s2 = w2.x * a2.x + w2.y * a2.y + w2.z * a2.z + w2.w * a2.w;
        float s3 = w3.x * a3.x + w3.y * a3.y + w3.z * a3.z + w3.w * a3.w;
        float s = (s0 + s1) + (s2 + s3);

        s += __shfl_down_sync(0xffffffffu, s, 16);
        s += __shfl_down_sync(0xffffffffu, s, 8);
        s += __shfl_down_sync(0xffffffffu, s, 4);
        s += __shfl_down_sync(0xffffffffu, s, 2);
        s += __shfl_down_sync(0xffffffffu, s, 1);
        __shared__ float sp[8];
        int lane = tid & 31, wid = tid >> 5;
        if (lane == 0) sp[wid] = s;
        __syncthreads();
        if (tid == 0) {
            float t = 0.f;
            #pragma unroll
            for (int k = 0; k < 8; k++) t += sp[k];
            out[o] = t + bias[o];
        }
    }
}

extern "C" void kernel_launch(void* const* d_in, const int* in_sizes, int n_in,
                              void* d_out, int out_size) {
    const float* A  = (const float*)d_in[0];  // adjacency [N,N]
    const float* E  = (const float*)d_in[1];  // edge_features [N,F]
    const float* Wm = (const float*)d_in[2];  // W [OUT,N]
    const float* b  = (const float*)d_in[3];  // b [OUT]
    float* out = (float*)d_out;

    prep_kernel<<<PACK_BLOCKS + Nn, 256>>>(A, E);
    fused_kernel<<<AGG_BLOCKS + Nn, 256>>>(Wm, b, out);
}

// round 13
// speedup vs baseline: 1.0882x; 1.0468x over previous
#include <cuda_runtime.h>
#include <cstdint>

#define Nn 4096
#define WORDS 128          // 4096 bits / 32
#define TI 16              // i-rows per agg block
#define JSPLIT 4           // j-range split per tile
#define NTILES (Nn / TI)   // 256
#define AGG_BLOCKS (NTILES * JSPLIT)   // 1024
#define PACK_BLOCKS 4096

// Scratch (device globals — no allocation allowed). All mutable state is
// re-zeroed by fixup_kernel at the END of every call (zero-init covers call 1).
__device__ __align__(16) uint32_t g_bitsR[Nn * WORDS];  // row-major bitsets
__device__ __align__(16) uint32_t g_w0[Nn];             // word-0 plane (fast test)
__device__ __align__(16) float g_e[Nn];    // row sums of edge_features
__device__ __align__(16) float g_agg[Nn];  // exact aggregated[i] (verification)
__device__ float g_S;                      // sum of all e[j]
__device__ int   g_tile_cnt[NTILES];       // per-tile chunk-completion counters
__device__ int   g_ndev;                   // deviation count
__device__ int   g_devi[Nn];               // deviation indices
__device__ float g_devv[Nn];               // deviation values

// ---------------------------------------------------------------------------
// K1: pack A (FMA packing, diag cleared at write) + rowsum E (also accumulate
// the global scalar S = sum(e) via one atomicAdd per row-block).
// ---------------------------------------------------------------------------
__global__ void prep_kernel(const float* __restrict__ A,
                            const float* __restrict__ E) {
    if (blockIdx.x < PACK_BLOCKS) {
        int lane = threadIdx.x & 31;
        int warpid = blockIdx.x * 8 + (threadIdx.x >> 5);   // 0..32767
        const int NW = PACK_BLOCKS * 8;                     // 32768 warps
        unsigned q = lane >> 2;                             // word-in-group (0..7)
        unsigned grpmask = 0xFu << (q << 2);
        unsigned sh = (lane & 3) * 8;
        #pragma unroll
        for (int o = 0; o < 2; o++) {
            int gg  = warpid + o * NW;
            int j   = gg >> 4;
            int grp = gg & 15;
            int col = (grp << 8) + (lane << 3);
            const float4* p = (const float4*)(A + (size_t)j * Nn + col);
            float4 v0 = __ldcs(p);
            float4 v1 = __ldcs(p + 1);
            float f = v0.x;
            f = fmaf(v0.y,   2.f, f);
            f = fmaf(v0.z,   4.f, f);
            f = fmaf(v0.w,   8.f, f);
            f = fmaf(v1.x,  16.f, f);
            f = fmaf(v1.y,  32.f, f);
            f = fmaf(v1.z,  64.f, f);
            f = fmaf(v1.w, 128.f, f);
            unsigned byte = (unsigned)f;          // exact: distinct powers of 2
            unsigned word = __reduce_or_sync(grpmask, byte << sh);
            if ((lane & 3) == 0) {
                int w = (grp << 3) + (int)q;
                if (w == (j >> 5)) word &= ~(1u << (j & 31));   // clear diag bit
                g_bitsR[j * WORDS + w] = word;
                if (w == 0) g_w0[j] = word;
            }
        }
    } else {
        int j = blockIdx.x - PACK_BLOCKS;
        const float4* row = (const float4*)(E + (size_t)j * Nn);
        int tid = threadIdx.x;
        float s = 0.f;
        #pragma unroll
        for (int k = 0; k < 4; k++) {
            float4 v = __ldcs(row + tid + 256 * k);
            s += (v.x + v.y) + (v.z + v.w);
        }
        s += __shfl_down_sync(0xffffffffu, s, 16);
        s += __shfl_down_sync(0xffffffffu, s, 8);
        s += __shfl_down_sync(0xffffffffu, s, 4);
        s += __shfl_down_sync(0xffffffffu, s, 2);
        s += __shfl_down_sync(0xffffffffu, s, 1);
        __shared__ float sp[8];
        int lane = tid & 31, wid = tid >> 5;
        if (lane == 0) sp[wid] = s;
        __syncthreads();
        if (tid == 0) {
            float t = 0.f;
            #pragma unroll
            for (int k = 0; k < 8; k++) t += sp[k];
            g_e[j] = t;
            atomicAdd(&g_S, t);
        }
    }
}

// ---------------------------------------------------------------------------
// K2 (independent agg + gemv, interleaved 1:4 so every wave mixes ALU-bound
// agg with DRAM-bound gemv):
//  b%5==0 : agg block — exact agg[i] (subtract-on-miss bitsets). The LAST
//           chunk per tile computes delta[i] = (S - e[i]) - agg[i] and appends
//           any |delta| > 0.5 to the deviation list (expected: none; noise
//           level is ~1e-2, a real deviation is ~|e| ~ 64).
//  else    : gemv row o — out[o] = S*rowsum(W[o]) - dot(W[o], e) + b[o].
//           NO dependency on agg. K3 applies the (expected-empty) correction.
// ---------------------------------------------------------------------------
__global__ void main2_kernel(const float* __restrict__ Wm,
                             const float* __restrict__ bias,
                             float* __restrict__ out) {
    int b = blockIdx.x;
    int tid = threadIdx.x;

    if (b % 5 == 0) {
        int id = b / 5;                   // 0..AGG_BLOCKS-1
        int tile  = id & (NTILES - 1);
        int chunk = id >> 8;              // 0..JSPLIT-1
        int i0 = tile * TI;

        __shared__ uint32_t sBi[TI * WORDS];
        __shared__ int sNe[TI];
        __shared__ float sPart[8][TI];
        __shared__ int sLast;

        if (tid < TI) sNe[tid] = 0;
        __syncthreads();
        {   // coalesced i-tile load: 8KB contiguous
            const uint4* src = (const uint4*)(g_bitsR + (size_t)i0 * WORDS);
            uint4* dst = (uint4*)sBi;
            #pragma unroll
            for (int k = 0; k < (TI * WORDS / 4) / 256; k++) {
                uint4 v = src[tid + 256 * k];
                dst[tid + 256 * k] = v;
                if (v.x | v.y | v.z | v.w) sNe[(tid + 256 * k) >> 5] = 1;
            }
        }
        __syncthreads();

        int jBeg = chunk * (Nn / JSPLIT);
        int jEnd = jBeg + (Nn / JSPLIT);

        float sumE = 0.f;
        for (int j = jBeg + tid; j < jEnd; j += blockDim.x) sumE += g_e[j];

        uint32_t bi0[TI];
        float acc[TI];
        #pragma unroll
        for (int r = 0; r < TI; r++) { bi0[r] = sBi[r * WORDS]; acc[r] = sumE; }

        for (int j = jBeg + tid; j < jEnd; j += blockDim.x) {
            uint32_t b0 = g_w0[j];
            unsigned zmask = 0;
            #pragma unroll
            for (int r = 0; r < TI; r++) {
                if (!(bi0[r] & b0)) zmask |= (1u << r);
            }
            if (zmask) {                  // rare (~1e-4 per pair)
                float e = g_e[j];
                const uint32_t* bj = g_bitsR + (size_t)j * WORDS;
                do {
                    int r = __ffs(zmask) - 1;
                    zmask &= zmask - 1;
                    bool hit = false;
                    for (int w = 1; w < WORDS; w++)
                        if (sBi[r * WORDS + w] & bj[w]) { hit = true; break; }
                    if (!hit) acc[r] -= e;
                } while (zmask);
            }
        }

        int lane = tid & 31, wid = tid >> 5;
        #pragma unroll
        for (int r = 0; r < TI; r++) {
            float v = acc[r];
            v += __shfl_down_sync(0xffffffffu, v, 16);
            v += __shfl_down_sync(0xffffffffu, v, 8);
            v += __shfl_down_sync(0xffffffffu, v, 4);
            v += __shfl_down_sync(0xffffffffu, v, 2);
            v += __shfl_down_sync(0xffffffffu, v, 1);
            if (lane == 0) sPart[wid][r] = v;
        }
        __syncthreads();
        if (tid < TI) {
            float s = 0.f;
            #pragma unroll
            for (int w = 0; w < 8; w++) s += sPart[w][tid];
            int i = i0 + tid;
            if (i >= jBeg && i < jEnd && sNe[tid]) s -= g_e[i];  // diag fix
            atomicAdd(&g_agg[i], s);
            __threadfence();              // release our contribution
        }
        __syncthreads();
        if (tid == 0) {
            int old = atomicAdd(&g_tile_cnt[tile], 1);
            sLast = (old == JSPLIT - 1);
        }
        __syncthreads();
        if (sLast && tid < TI) {
            __threadfence();              // acquire other chunks' atomics
            int i = i0 + tid;
            float a;
            asm volatile("ld.global.cg.f32 %0, [%1];" : "=f"(a) : "l"(&g_agg[i]));
            float delta = (g_S - g_e[i]) - a;
            if (fabsf(delta) > 0.5f) {
                int pos = atomicAdd(&g_ndev, 1);
                g_devi[pos] = i;
                g_devv[pos] = delta;
            }
        }
    } else {
        // ---- gemv row o: no dependency on agg ----
        int o = b - b / 5 - 1;
        const float4* wr = (const float4*)(Wm + (size_t)o * Nn);
        const float4* er = (const float4*)g_e;
        float4 w0 = __ldcs(wr + tid);
        float4 w1 = __ldcs(wr + tid + 256);
        float4 w2 = __ldcs(wr + tid + 512);
        float4 w3 = __ldcs(wr + tid + 768);
        float4 e0 = er[tid];
        float4 e1 = er[tid + 256];
        float4 e2 = er[tid + 512];
        float4 e3 = er[tid + 768];
        // dot(W,e) and rowsum(W) in one pass
        float d = w0.x * e0.x + w0.y * e0.y + w0.z * e0.z + w0.w * e0.w;
        d += w1.x * e1.x + w1.y * e1.y + w1.z * e1.z + w1.w * e1.w;
        d += w2.x * e2.x + w2.y * e2.y + w2.z * e2.z + w2.w * e2.w;
        d += w3.x * e3.x + w3.y * e3.y + w3.z * e3.z + w3.w * e3.w;
        float r = (w0.x + w0.y) + (w0.z + w0.w);
        r += (w1.x + w1.y) + (w1.z + w1.w);
        r += (w2.x + w2.y) + (w2.z + w2.w);
        r += (w3.x + w3.y) + (w3.z + w3.w);

        d += __shfl_down_sync(0xffffffffu, d, 16);
        r += __shfl_down_sync(0xffffffffu, r, 16);
        d += __shfl_down_sync(0xffffffffu, d, 8);
        r += __shfl_down_sync(0xffffffffu, r, 8);
        d += __shfl_down_sync(0xffffffffu, d, 4);
        r += __shfl_down_sync(0xffffffffu, r, 4);
        d += __shfl_down_sync(0xffffffffu, d, 2);
        r += __shfl_down_sync(0xffffffffu, r, 2);
        d += __shfl_down_sync(0xffffffffu, d, 1);
        r += __shfl_down_sync(0xffffffffu, r, 1);
        __shared__ float spd[8], spr[8];
        int lane = tid & 31, wid = tid >> 5;
        if (lane == 0) { spd[wid] = d; spr[wid] = r; }
        __syncthreads();
        if (tid == 0) {
            float td = 0.f, tr = 0.f;
            #pragma unroll
            for (int k = 0; k < 8; k++) { td += spd[k]; tr += spr[k]; }
            out[o] = g_S * tr - td + bias[o];
        }
    }
}

// ---------------------------------------------------------------------------
// K3 (single block): apply deviation corrections (expected: zero entries),
// then re-zero all mutable state for the next graph replay.
// ---------------------------------------------------------------------------
__global__ void fixup_kernel(const float* __restrict__ Wm,
                             float* __restrict__ out) {
    int tid = threadIdx.x;
    int nd = g_ndev;                      // same value seen by all threads
    if (nd > 0) {
        for (int o = tid; o < Nn; o += 256) {
            float c = 0.f;
            for (int k = 0; k < nd; k++)
                c += g_devv[k] * Wm[(size_t)o * Nn + g_devi[k]];
            out[o] -= c;
        }
    }
    __syncthreads();
    // reset state for next call
    float4 z4 = make_float4(0.f, 0.f, 0.f, 0.f);
    float4* a4 = (float4*)g_agg;
    #pragma unroll
    for (int k = 0; k < 4; k++) a4[tid + 256 * k] = z4;
    if (tid < NTILES) g_tile_cnt[tid] = 0;
    if (tid == 0) { g_S = 0.f; g_ndev = 0; }
}

extern "C" void kernel_launch(void* const* d_in, const int* in_sizes, int n_in,
                              void* d_out, int out_size) {
    const float* A  = (const float*)d_in[0];  // adjacency [N,N]
    const float* E  = (const float*)d_in[1];  // edge_features [N,F]
    const float* Wm = (const float*)d_in[2];  // W [OUT,N]
    const float* b  = (const float*)d_in[3];  // b [OUT]
    float* out = (float*)d_out;

    prep_kernel<<<PACK_BLOCKS + Nn, 256>>>(A, E);
    main2_kernel<<<AGG_BLOCKS + Nn, 256>>>(Wm, b, out);
    fixup_kernel<<<1, 256>>>(Wm, out);
}